// round 8
// baseline (speedup 1.0000x reference)
#include <cuda_runtime.h>
#include <cuda_bf16.h>
#include <cstdint>
#include <cstddef>

// Problem constants
#define BB   8
#define CIN  64
#define COUT 64
#define HH   256
#define WW   256

// Fixed-point scales: x ~ N(0,1) -> S_X = 2^12 (range +-7.97, 16-bit);
// w = 0.05*N*alpha -> S_W = 2^16 (range +-0.498, 16-bit). Quant err ~1.5e-4 rel.
#define SXF 4096.0f
#define SWF 65536.0f

// ---------------------------------------------------------------------------
// Device scratch (allocation-free rule: __device__ globals)
// ---------------------------------------------------------------------------
__device__ signed char g_x8h[(size_t)BB * HH * WW * CIN];     // 32 MB NHWC hi limb
__device__ signed char g_x8l[(size_t)BB * HH * WW * CIN];     // 32 MB NHWC lo limb
__device__ signed char g_w8[(size_t)BB * 9 * 2 * COUT * CIN]; // [b][tap][limb][co][ci]

// ---------------------------------------------------------------------------
// Helpers
// ---------------------------------------------------------------------------
__device__ __forceinline__ uint32_t smem_u32(const void* p) {
    uint32_t a;
    asm("{ .reg .u64 t; cvta.to.shared.u64 t, %1; cvt.u32.u64 %0, t; }"
        : "=r"(a) : "l"(p));
    return a;
}
// 64B-row swizzle: XOR 16B-segment bits [5:4] with row bits [8:7].
// With 64B rows this makes 8 consecutive rows hit 8 distinct 16B bank slots.
#define ASWZ(o) ((o) ^ (((o) >> 3) & 0x30))

#define STS128(a, v) \
    asm volatile("st.shared.v4.b32 [%0], {%1,%2,%3,%4};" \
                 :: "r"(a), "r"((v).x), "r"((v).y), "r"((v).z), "r"((v).w) : "memory")
#define STS64(a, v0, v1) \
    asm volatile("st.shared.v2.b32 [%0], {%1,%2};" \
                 :: "r"(a), "r"(v0), "r"(v1) : "memory")
#define LDSM4(r0, r1, r2, r3, a) \
    asm volatile("ldmatrix.sync.aligned.m8n8.x4.shared.b16 {%0,%1,%2,%3}, [%4];" \
                 : "=r"(r0), "=r"(r1), "=r"(r2), "=r"(r3) : "r"(a))

__device__ __forceinline__ void imma16832(int* c, const uint32_t* a,
                                          const uint32_t* b) {
    asm volatile(
        "mma.sync.aligned.m16n8k32.row.col.s32.s8.s8.s32 "
        "{%0,%1,%2,%3}, {%4,%5,%6,%7}, {%8,%9}, {%0,%1,%2,%3};"
        : "+r"(c[0]), "+r"(c[1]), "+r"(c[2]), "+r"(c[3])
        : "r"(a[0]), "r"(a[1]), "r"(a[2]), "r"(a[3]), "r"(b[0]), "r"(b[1]));
}

// ---------------------------------------------------------------------------
// Pre-pass 1: x NCHW f32 -> NHWC s8 hi/lo limbs.  grid (256 h, 8 b), 256 thr.
// ---------------------------------------------------------------------------
__global__ void xcvt_kernel(const float* __restrict__ x) {
    __shared__ float tile[64][65];
    const int h = blockIdx.x, b = blockIdx.y;
    const int t = threadIdx.x;
    for (int w0 = 0; w0 < WW; w0 += 64) {
        {
            const int ci0 = t >> 6, w = t & 63;
#pragma unroll
            for (int k = 0; k < 16; ++k) {
                int ci = ci0 + k * 4;
                tile[ci][w] = x[(((size_t)b * CIN + ci) * HH + h) * WW + w0 + w];
            }
        }
        __syncthreads();
        {
            const int c8 = t & 7;        // channel-octet
            const int p0 = t >> 3;       // 0..31
#pragma unroll
            for (int m = 0; m < 2; ++m) {
                const int p = p0 + m * 32;
                uint32_t hA = 0, hB = 0, lA = 0, lB = 0;
#pragma unroll
                for (int jj = 0; jj < 8; ++jj) {
                    float v = tile[c8 * 8 + jj][p];
                    int iv = __float2int_rn(v * SXF);
                    iv = max(-32640, min(32639, iv));
                    int hi = (iv + 128) >> 8;          // round-to-nearest split
                    int lo = iv - (hi << 8);           // in [-128,127]
                    uint32_t hb = (uint32_t)(hi & 0xFF);
                    uint32_t lb = (uint32_t)(lo & 0xFF);
                    if (jj < 4) { hA |= hb << (jj * 8); lA |= lb << (jj * 8); }
                    else        { hB |= hb << ((jj - 4) * 8); lB |= lb << ((jj - 4) * 8); }
                }
                size_t o = (((size_t)b * HH + h) * WW + w0 + p) * CIN + c8 * 8;
                *(uint2*)(g_x8h + o) = make_uint2(hA, hB);
                *(uint2*)(g_x8l + o) = make_uint2(lA, lB);
            }
        }
        __syncthreads();
    }
}

// ---------------------------------------------------------------------------
// Pre-pass 2: alpha-folded weights -> s8 hi/lo [b][tap][limb][co][ci].
// ---------------------------------------------------------------------------
__global__ void wcvt_kernel(const float* __restrict__ weight,
                            const float* __restrict__ alpha) {
    int idx = blockIdx.x * 256 + threadIdx.x;
    if (idx >= BB * 9 * COUT * CIN) return;
    int ci = idx & 63;
    int co = (idx >> 6) & 63;
    int rest = idx >> 12;                 // b*9 + tap
    int tap = rest % 9;
    float v = weight[(co * CIN + ci) * 9 + tap] * alpha[(rest / 9) * CIN + ci];
    int iv = __float2int_rn(v * SWF);
    iv = max(-32640, min(32639, iv));
    int hi = (iv + 128) >> 8;
    int lo = iv - (hi << 8);
    g_w8[(size_t)rest * 8192 + co * 64 + ci] = (signed char)hi;
    g_w8[(size_t)rest * 8192 + 4096 + co * 64 + ci] = (signed char)lo;
}

// ---------------------------------------------------------------------------
// Main conv: imma.m16n8k32 s8 implicit GEMM, 2-limb 16-bit fixed point.
// CTA: 1 h-row x 128 w x 64 co.  grid (2 wblk, 256 h, 8 b).  512 thr = 16 warps.
// Warp: wchunk = warp&7 (16 px), cohalf = warp>>3 (32 co).
// 4 products: Ah*Bh -> cH, Ah*Bl + Al*Bh -> cX, Al*Bl -> cL (all exact s32).
// SMEM (1024-aligned base):
//   A: 6 line-limbs (3 input rows x {hi,lo}) of 8704B (130 px x 64B used)
//   B: 2 tap-parity bufs x 8192B (hi at +0, lo at +4096)
//   bias: 256B
// ---------------------------------------------------------------------------
#define ALINE    8704
#define SM_B     (6 * ALINE)           // 52224
#define SM_BIAS  (SM_B + 16384)        // 68608
#define SMEM_REQ (SM_BIAS + 256 + 1024)
#define NTH      512

__global__ __launch_bounds__(NTH, 1)
void conv_mma_kernel(const float* __restrict__ bias, float* __restrict__ out) {
    extern __shared__ char smem_raw[];
    const uint32_t sraw = smem_u32(smem_raw);
    const uint32_t sb = (sraw + 1023) & ~1023u;
    char* g = smem_raw + (sb - sraw);

    const int tid = threadIdx.x;
    const int warp = tid >> 5;
    const int lane = tid & 31;
    const int w0 = blockIdx.x * 128;
    const int h0 = blockIdx.y;
    const int b = blockIdx.z;

    const int wchunk = warp & 7;
    const int cohalf = warp >> 3;

    if (tid < 64) ((float*)(g + SM_BIAS))[tid] = bias[tid];

    // ---- load 3 input rows (hi+lo limbs): 130 px x 64 ci s8, swizzled ----
    {
        const int c8 = tid & 7;        // 8B ci-group
        const int jr = tid >> 3;       // 0..63
        for (int l = 0; l < 3; ++l) {
            const int gh = h0 - 1 + l;
            const bool hok = (gh >= 0) && (gh < HH);
            const uint32_t bhA = sb + (l * 2 + 0) * ALINE;
            const uint32_t blA = sb + (l * 2 + 1) * ALINE;
#pragma unroll
            for (int it = 0; it < 3; ++it) {
                int j = it * 64 + jr;          // 0..191
                if (j < 130) {
                    int gw = w0 - 1 + j;
                    uint2 vh = make_uint2(0, 0), vl = make_uint2(0, 0);
                    if (hok && gw >= 0 && gw < WW) {
                        size_t o = (((size_t)b * HH + gh) * WW + gw) * CIN + c8 * 8;
                        vh = *(const uint2*)(g_x8h + o);
                        vl = *(const uint2*)(g_x8l + o);
                    }
                    uint32_t so = ASWZ((uint32_t)(j * 64 + c8 * 8));
                    STS64(bhA + so, vh.x, vh.y);
                    STS64(blA + so, vl.x, vl.y);
                }
            }
        }
    }

    // ---- load B for tap 0 into buffer 0 (8192B, 512 thr x 16B) ----
    {
        const signed char* src = g_w8 + (size_t)(b * 9) * 8192;
        uint32_t o = (uint32_t)tid * 16;
        uint4 v = *(const uint4*)(src + o);
        STS128(sb + SM_B + (o & 4096) + ASWZ(o & 4095), v);
    }
    __syncthreads();

    // ---- accumulators (exact s32) ----
    int cH[4][4], cX[4][4], cL[4][4];
#pragma unroll
    for (int n = 0; n < 4; ++n)
#pragma unroll
        for (int r = 0; r < 4; ++r) { cH[n][r] = 0; cX[n][r] = 0; cL[n][r] = 0; }

    // per-lane ldmatrix address components
    const int pj  = wchunk * 16 + (lane & 7) + ((lane >> 3) & 1) * 8;  // px row part
    const int kbA = (lane >> 4) * 16;
    const int coB = cohalf * 32 + (lane & 7) + (lane >> 4) * 8;        // + copair*16
    const int kbB = ((lane >> 3) & 1) * 16;

    for (int tap = 0; tap < 9; ++tap) {
        const int cur = tap & 1;
        const int kh = tap / 3, kw = tap - kh * 3;

        // prefetch next tap's B into registers
        uint4 pf;
        if (tap < 8) {
            const signed char* src = g_w8 + (size_t)(b * 9 + tap + 1) * 8192;
            pf = *(const uint4*)(src + (uint32_t)tid * 16);
        }

        const uint32_t aH = sb + (uint32_t)(kh * 2 + 0) * ALINE;
        const uint32_t aL = aH + ALINE;
        const uint32_t bB = sb + SM_B + (uint32_t)cur * 8192;
        const int jrow = pj + kw;                  // tile px row, max 129

#pragma unroll
        for (int kc = 0; kc < 2; ++kc) {
            uint32_t ao = ASWZ((uint32_t)(jrow * 64 + kc * 32 + kbA));
            uint32_t ah[4], al[4];
            LDSM4(ah[0], ah[1], ah[2], ah[3], aH + ao);
            LDSM4(al[0], al[1], al[2], al[3], aL + ao);
#pragma unroll
            for (int cp = 0; cp < 2; ++cp) {
                uint32_t bo = ASWZ(
                    (uint32_t)((coB + cp * 16) * 64 + kc * 32 + kbB));
                uint32_t bh[4], bl[4];
                LDSM4(bh[0], bh[1], bh[2], bh[3], bB + bo);
                LDSM4(bl[0], bl[1], bl[2], bl[3], bB + 4096 + bo);
#pragma unroll
                for (int nt = 0; nt < 2; ++nt) {
                    const int n = cp * 2 + nt;
                    imma16832(cH[n], ah, bh + 2 * nt);   // hi*hi   (2^16)
                    imma16832(cX[n], ah, bl + 2 * nt);   // hi*lo   (2^8)
                    imma16832(cX[n], al, bh + 2 * nt);   // lo*hi   (2^8)
                    imma16832(cL[n], al, bl + 2 * nt);   // lo*lo   (2^0)
                }
            }
        }

        if (tap < 8) {
            uint32_t o = (uint32_t)tid * 16;
            STS128(sb + SM_B + (uint32_t)(cur ^ 1) * 8192 + (o & 4096) +
                       ASWZ(o & 4095),
                   pf);
            __syncthreads();
        }
    }

    // ---- epilogue: recombine limbs, add bias, store ----
    // out = bias + (cH*2^16 + cX*2^8 + cL) / (S_X*S_W) ; S_X*S_W = 2^28
    const float k1 = 2.44140625e-4f;              // 2^-12
    const float k2 = 9.5367431640625e-7f;         // 2^-20
    const float k3 = 3.725290298461914e-9f;       // 2^-28
    const float* biasS = (const float*)(g + SM_BIAS);
    const int px0 = w0 + wchunk * 16 + (lane >> 2);
#pragma unroll
    for (int n = 0; n < 4; ++n) {
        const int co = cohalf * 32 + n * 8 + (lane & 3) * 2;
        const float b0 = biasS[co], b1 = biasS[co + 1];
        float* p = out + (((size_t)b * COUT + co) * HH + h0) * WW + px0;
        p[0] = b0 + (float)cH[n][0] * k1 + (float)cX[n][0] * k2 + (float)cL[n][0] * k3;
        p[(size_t)HH * WW] =
            b1 + (float)cH[n][1] * k1 + (float)cX[n][1] * k2 + (float)cL[n][1] * k3;
        p[8] = b0 + (float)cH[n][2] * k1 + (float)cX[n][2] * k2 + (float)cL[n][2] * k3;
        p[(size_t)HH * WW + 8] =
            b1 + (float)cH[n][3] * k1 + (float)cX[n][3] * k2 + (float)cL[n][3] * k3;
    }
}

// ---------------------------------------------------------------------------
// Launch. Inputs: x, alpha, weight, bias. Output: float32 NCHW.
// ---------------------------------------------------------------------------
extern "C" void kernel_launch(void* const* d_in, const int* in_sizes, int n_in,
                              void* d_out, int out_size) {
    const float* x      = (const float*)d_in[0];
    const float* alpha  = (const float*)d_in[1];
    const float* weight = (const float*)d_in[2];
    const float* bias   = (const float*)d_in[3];
    float* out = (float*)d_out;
    (void)in_sizes; (void)n_in; (void)out_size;

    cudaFuncSetAttribute(conv_mma_kernel,
                         cudaFuncAttributeMaxDynamicSharedMemorySize, SMEM_REQ);

    xcvt_kernel<<<dim3(HH, BB), 256>>>(x);
    {
        int n = BB * 9 * COUT * CIN;
        wcvt_kernel<<<(n + 255) / 256, 256>>>(weight, alpha);
    }
    conv_mma_kernel<<<dim3(2, HH, BB), NTH, SMEM_REQ>>>(bias, out);
}

// round 9
// speedup vs baseline: 6.3980x; 6.3980x over previous
#include <cuda_runtime.h>
#include <cuda_fp16.h>
#include <cstdint>
#include <cstddef>

// Problem constants
#define BB   8
#define CIN  64
#define COUT 64
#define HH   256
#define WW   256

// ---------------------------------------------------------------------------
// Device scratch (allocation-free rule: __device__ globals)
// ---------------------------------------------------------------------------
__device__ __half g_xh[(size_t)BB * HH * WW * CIN];     // 64 MB, NHWC fp16
__device__ __half g_w[(size_t)BB * 9 * 2 * COUT * CIN]; // [b][tap][limb][co][ci]

// ---------------------------------------------------------------------------
// Helpers
// ---------------------------------------------------------------------------
__device__ __forceinline__ uint32_t smem_u32(const void* p) {
    uint32_t a;
    asm("{ .reg .u64 t; cvta.to.shared.u64 t, %1; cvt.u32.u64 %0, t; }"
        : "=r"(a) : "l"(p));
    return a;
}
#define SWZ(o) ((o) ^ (((o) >> 3) & 0x70))

#define STS128(a, v) \
    asm volatile("st.shared.v4.b32 [%0], {%1,%2,%3,%4};" \
                 :: "r"(a), "r"((v).x), "r"((v).y), "r"((v).z), "r"((v).w) : "memory")

#define LDSM4(r0, r1, r2, r3, a) \
    asm volatile("ldmatrix.sync.aligned.m8n8.x4.shared.b16 {%0,%1,%2,%3}, [%4];" \
                 : "=r"(r0), "=r"(r1), "=r"(r2), "=r"(r3) : "r"(a))

__device__ __forceinline__ void mma16816(float* c, const uint32_t* a,
                                         const uint32_t* b) {
    asm volatile(
        "mma.sync.aligned.m16n8k16.row.col.f32.f16.f16.f32 "
        "{%0,%1,%2,%3}, {%4,%5,%6,%7}, {%8,%9}, {%0,%1,%2,%3};"
        : "+f"(c[0]), "+f"(c[1]), "+f"(c[2]), "+f"(c[3])
        : "r"(a[0]), "r"(a[1]), "r"(a[2]), "r"(a[3]), "r"(b[0]), "r"(b[1]));
}

// ---------------------------------------------------------------------------
// Pre-pass 1: x NCHW fp32 -> NHWC fp16 (single).  grid (256 h, 8 b), 256 thr.
// ---------------------------------------------------------------------------
__global__ void xcvt_kernel(const float* __restrict__ x) {
    __shared__ float tile[64][65];
    const int h = blockIdx.x, b = blockIdx.y;
    const int t = threadIdx.x;
    for (int w0 = 0; w0 < WW; w0 += 64) {
        {
            const int ci0 = t >> 6, w = t & 63;
#pragma unroll
            for (int k = 0; k < 16; ++k) {
                int ci = ci0 + k * 4;
                tile[ci][w] = x[(((size_t)b * CIN + ci) * HH + h) * WW + w0 + w];
            }
        }
        __syncthreads();
        {
            const int c8 = t & 7;        // channel-octet
            const int p0 = t >> 3;       // 0..31
#pragma unroll
            for (int m = 0; m < 2; ++m) {
                const int p = p0 + m * 32;
                uint32_t q[4];
#pragma unroll
                for (int jj = 0; jj < 4; ++jj) {
                    __half h0 = __float2half_rn(tile[c8 * 8 + jj * 2][p]);
                    __half h1 = __float2half_rn(tile[c8 * 8 + jj * 2 + 1][p]);
                    q[jj] = (uint32_t)*(uint16_t*)&h0 |
                            ((uint32_t)*(uint16_t*)&h1 << 16);
                }
                size_t o = (((size_t)b * HH + h) * WW + w0 + p) * CIN + c8 * 8;
                *(uint4*)&g_xh[o] = make_uint4(q[0], q[1], q[2], q[3]);
            }
        }
        __syncthreads();
    }
}

// ---------------------------------------------------------------------------
// Pre-pass 2: alpha-folded weights -> [b][tap][limb][co][ci] fp16 hi/lo.
// ---------------------------------------------------------------------------
__global__ void wcvt_kernel(const float* __restrict__ weight,
                            const float* __restrict__ alpha) {
    int idx = blockIdx.x * 256 + threadIdx.x;
    if (idx >= BB * 9 * COUT * CIN) return;
    int ci = idx & 63;
    int co = (idx >> 6) & 63;
    int rest = idx >> 12;         // b*9 + tap
    float v = weight[(co * CIN + ci) * 9 + rest % 9] * alpha[(rest / 9) * CIN + ci];
    __half hi = __float2half_rn(v);
    __half lo = __float2half_rn(v - __half2float(hi));
    g_w[(size_t)(rest * 2 + 0) * 4096 + co * 64 + ci] = hi;
    g_w[(size_t)(rest * 2 + 1) * 4096 + co * 64 + ci] = lo;
}

// ---------------------------------------------------------------------------
// Main conv: mma.sync fp16 implicit GEMM, 512 threads = 16 warps (4/SMSP).
// CTA: 2 h-rows x 128 w x 64 cout.  grid (2, 128, 8).
// Warp: cohalf = warp&1 (32 co), wchunk = (warp>>1)&3 (32 px), hline = warp>>3.
// Asymmetric split: x fp16 single; w = wh + wl (fp16 pair).
//   accP += X*Wh,  accQ += X*Wl; out = accP + accQ (+bias).
// SMEM (1024-aligned base):
//   A: 4 halo-line bufs, 130 rows x 128B, padded to 17408B
//   B: 2 tap-parity bufs x 16384B (hi at +0, lo at +8192)
//   bias: 256B
// ---------------------------------------------------------------------------
#define ABUF     17408
#define SM_B     (4 * ABUF)            // 69632
#define SM_BIAS  (SM_B + 32768)        // 102400
#define SMEM_REQ (SM_BIAS + 256 + 1024)
#define NTH      512

__global__ __launch_bounds__(NTH, 1)
void conv_mma_kernel(const float* __restrict__ bias, float* __restrict__ out) {
    extern __shared__ char smem_raw[];
    const uint32_t sraw = smem_u32(smem_raw);
    const uint32_t sb = (sraw + 1023) & ~1023u;
    char* g = smem_raw + (sb - sraw);

    const int tid = threadIdx.x;
    const int warp = tid >> 5;
    const int lane = tid & 31;
    const int b = blockIdx.z;
    const int h0 = blockIdx.y * 2;
    const int w0 = blockIdx.x * 128;

    const int cohalf = warp & 1;
    const int wchunk = (warp >> 1) & 3;
    const int hline = warp >> 3;

    if (tid < 64) ((float*)(g + SM_BIAS))[tid] = bias[tid];

    // ---- load 4 halo lines: 130 rows x 64ci fp16, SW128-swizzled ----
    {
        const int c8 = tid & 7;        // 16B ci-group
        const int jr = tid >> 3;       // 0..63
        for (int l = 0; l < 4; ++l) {
            const int gh = h0 + l - 1;
            const bool hok = (gh >= 0) && (gh < HH);
            const uint32_t ba = sb + l * ABUF;
#pragma unroll
            for (int it = 0; it < 3; ++it) {
                int j = it * 64 + jr;          // 0..191
                if (j < 130) {
                    int gw = w0 - 1 + j;
                    uint4 vh = make_uint4(0, 0, 0, 0);
                    if (hok && gw >= 0 && gw < WW) {
                        size_t o = (((size_t)b * HH + gh) * WW + gw) * CIN + c8 * 8;
                        vh = *(const uint4*)&g_xh[o];
                    }
                    STS128(ba + SWZ((uint32_t)(j * 128 + c8 * 16)), vh);
                }
            }
        }
    }

    // ---- load B for tap 0 into buffer 0 ----
    {
        const char* src = (const char*)g_w + (size_t)(b * 9) * 16384;
#pragma unroll
        for (int i = 0; i < 2; ++i) {
            uint32_t o = (uint32_t)(i * NTH + tid) * 16;
            uint4 v = *(const uint4*)(src + o);
            STS128(sb + SM_B + (o & 8192) + SWZ(o & 8191), v);
        }
    }
    __syncthreads();

    // ---- accumulators: accP bias-initialized, accQ zero ----
    float accP[2][4][4], accQ[2][4][4];
    {
        const float* biasS = (const float*)(g + SM_BIAS);
#pragma unroll
        for (int nb = 0; nb < 4; ++nb) {
            float b0 = biasS[cohalf * 32 + nb * 8 + (lane & 3) * 2];
            float b1 = biasS[cohalf * 32 + nb * 8 + (lane & 3) * 2 + 1];
#pragma unroll
            for (int mh = 0; mh < 2; ++mh) {
                accP[mh][nb][0] = b0; accP[mh][nb][1] = b1;
                accP[mh][nb][2] = b0; accP[mh][nb][3] = b1;
                accQ[mh][nb][0] = 0.f; accQ[mh][nb][1] = 0.f;
                accQ[mh][nb][2] = 0.f; accQ[mh][nb][3] = 0.f;
            }
        }
    }

    // per-lane ldmatrix address components
    const int arow = lane & 15;
    const uint32_t acoff = (uint32_t)(lane >> 4) * 16;
    const int brow = (lane & 7) + (lane >> 4) * 8;
    const uint32_t bcoff = (uint32_t)((lane >> 3) & 1) * 16;

    for (int tap = 0; tap < 9; ++tap) {
        const int cur = tap & 1;
        const int kh = tap / 3, kw = tap - kh * 3;

        // prefetch next tap's B into registers
        uint4 pf[2];
        if (tap < 8) {
            const char* src = (const char*)g_w + (size_t)(b * 9 + tap + 1) * 16384;
#pragma unroll
            for (int i = 0; i < 2; ++i)
                pf[i] = *(const uint4*)(src + (uint32_t)(i * NTH + tid) * 16);
        }

        const uint32_t aA = sb + (uint32_t)(hline + kh) * ABUF;
        const uint32_t bH = sb + SM_B + (uint32_t)cur * 16384;
        const uint32_t bL = bH + 8192;
        const int r0 = wchunk * 32 + kw + arow;       // + mh*16, max 129

#pragma unroll
        for (int kc = 0; kc < 4; ++kc) {
            const uint32_t co = (uint32_t)kc * 32 + acoff;
            uint32_t ah[2][4];
#pragma unroll
            for (int mh = 0; mh < 2; ++mh) {
                uint32_t off = SWZ((uint32_t)((r0 + mh * 16) * 128) + co);
                LDSM4(ah[mh][0], ah[mh][1], ah[mh][2], ah[mh][3], aA + off);
            }
#pragma unroll
            for (int nb2 = 0; nb2 < 2; ++nb2) {
                uint32_t boff = SWZ(
                    (uint32_t)((cohalf * 32 + nb2 * 16 + brow) * 128) +
                    (uint32_t)kc * 32 + bcoff);
                uint32_t bh[4], bl[4];
                LDSM4(bh[0], bh[1], bh[2], bh[3], bH + boff);
                LDSM4(bl[0], bl[1], bl[2], bl[3], bL + boff);
#pragma unroll
                for (int mh = 0; mh < 2; ++mh) {
                    mma16816(accP[mh][2 * nb2],     ah[mh], bh);      // X*Wh
                    mma16816(accP[mh][2 * nb2 + 1], ah[mh], bh + 2);
                    mma16816(accQ[mh][2 * nb2],     ah[mh], bl);      // X*Wl
                    mma16816(accQ[mh][2 * nb2 + 1], ah[mh], bl + 2);
                }
            }
        }

        if (tap < 8) {
            // store prefetched B into the other buffer; one sync per tap
#pragma unroll
            for (int i = 0; i < 2; ++i) {
                uint32_t o = (uint32_t)(i * NTH + tid) * 16;
                STS128(sb + SM_B + (uint32_t)(cur ^ 1) * 16384 + (o & 8192) +
                           SWZ(o & 8191),
                       pf[i]);
            }
            __syncthreads();
        }
    }

    // ---- epilogue: P+Q, direct stores ----
    const int hgl = h0 + hline;
#pragma unroll
    for (int mh = 0; mh < 2; ++mh) {
        const int wgl = w0 + wchunk * 32 + mh * 16 + (lane >> 2);
#pragma unroll
        for (int nb = 0; nb < 4; ++nb) {
            const int n0 = cohalf * 32 + nb * 8 + (lane & 3) * 2;
            float* p = out + (((size_t)b * COUT + n0) * HH + hgl) * WW + wgl;
            p[0] = accP[mh][nb][0] + accQ[mh][nb][0];
            p[(size_t)HH * WW] = accP[mh][nb][1] + accQ[mh][nb][1];
            p[8] = accP[mh][nb][2] + accQ[mh][nb][2];
            p[(size_t)HH * WW + 8] = accP[mh][nb][3] + accQ[mh][nb][3];
        }
    }
}

// ---------------------------------------------------------------------------
// Launch. Inputs: x, alpha, weight, bias. Output: float32 NCHW.
// ---------------------------------------------------------------------------
extern "C" void kernel_launch(void* const* d_in, const int* in_sizes, int n_in,
                              void* d_out, int out_size) {
    const float* x      = (const float*)d_in[0];
    const float* alpha  = (const float*)d_in[1];
    const float* weight = (const float*)d_in[2];
    const float* bias   = (const float*)d_in[3];
    float* out = (float*)d_out;
    (void)in_sizes; (void)n_in; (void)out_size;

    cudaFuncSetAttribute(conv_mma_kernel,
                         cudaFuncAttributeMaxDynamicSharedMemorySize, SMEM_REQ);

    xcvt_kernel<<<dim3(HH, BB), 256>>>(x);
    {
        int n = BB * 9 * COUT * CIN;
        wcvt_kernel<<<(n + 255) / 256, 256>>>(weight, alpha);
    }
    conv_mma_kernel<<<dim3(2, 128, BB), NTH, SMEM_REQ>>>(bias, out);
}